// round 5
// baseline (speedup 1.0000x reference)
#include <cuda_runtime.h>
#include <math.h>
#include <stdint.h>

#define NPTS 16384
#define MC   4096
#define DIMF 128
#define NH   4
#define DH   32
#define KNB  32
#define HID  512
#define RAD  0.3f
#define R2L  0.09000902f
#define CAP  512
#define CPB  8
#define CCH  512

// ---------------- scratch ----------------
__device__ int    g_idxc[MC];
__device__ float4 g_pts[NPTS];
__device__ __align__(16) float g_Qp[NPTS*DIMF];
__device__ __align__(16) float g_Kp[NPTS*DIMF];
__device__ __align__(16) float g_Vp[NPTS*DIMF];
__device__ int    g_nbr[MC*KNB];
__device__ int    g_cnt[MC];
__device__ unsigned long long g_nearKey[NPTS];
__device__ __align__(16) float g_ao[MC*DIMF];
__device__ __align__(16) float g_c1[MC*DIMF];
__device__ __align__(16) float g_hid[MC*HID];
__device__ __align__(16) float g_c2[MC*DIMF];

// ---------------- init: pack points + nearKey + idx dtype convert ----------------
__global__ void k_init(const float* __restrict__ xyz, const long long* __restrict__ raw) {
    int n = blockIdx.x * 256 + threadIdx.x;
    float x = xyz[3*n], y = xyz[3*n+1], z = xyz[3*n+2];
    g_pts[n] = make_float4(x, y, z, x*x + y*y + z*z);
    g_nearKey[n] = ~0ull;
    if (blockIdx.x == 0) {
        __shared__ int s_ok;
        if (threadIdx.x == 0) s_ok = 1;
        __syncthreads();
        for (int m = threadIdx.x; m < MC/2; m += 256) {
            long long v = raw[m];
            if (v < 0 || v >= NPTS) s_ok = 0;
        }
        __syncthreads();
        if (s_ok) {
            for (int m = threadIdx.x; m < MC; m += 256)
                g_idxc[m] = (int)raw[m];
        } else {
            const int* r32 = (const int*)raw;
            for (int m = threadIdx.x; m < MC; m += 256)
                g_idxc[m] = r32[m];
        }
    }
}

// ---------------- per-center radius filter + exact top-K by rank ----------------
__global__ __launch_bounds__(256) void k_topk() {
    __shared__ float cd[CPB][CAP];
    __shared__ int   ci[CPB][CAP];
    __shared__ int   s_cnt[CPB];
    const int tid = threadIdx.x;
    const int m0 = blockIdx.x * CPB;
    if (tid < CPB) s_cnt[tid] = 0;
    __syncthreads();

    float cx2[CPB], cy2[CPB], cz2[CPB], cc[CPB];
    #pragma unroll
    for (int g = 0; g < CPB; g++) {
        float4 c = g_pts[g_idxc[m0 + g]];
        cx2[g] = -2.f*c.x; cy2[g] = -2.f*c.y; cz2[g] = -2.f*c.z; cc[g] = c.w;
    }
    __syncthreads();

    for (int n = tid; n < NPTS; n += 256) {
        float4 p = g_pts[n];
        float rhs = R2L - p.w;
        #pragma unroll
        for (int g = 0; g < CPB; g++) {
            float t = fmaf(cx2[g], p.x, cc[g]);
            t = fmaf(cy2[g], p.y, t);
            t = fmaf(cz2[g], p.z, t);
            if (t < rhs) {
                float dist = sqrtf(fmaxf(t + p.w, 1e-12f));
                if (dist < RAD) {
                    int q = atomicAdd(&s_cnt[g], 1);
                    if (q < CAP) { cd[g][q] = dist; ci[g][q] = n; }
                }
            }
        }
    }
    __syncthreads();

    #pragma unroll
    for (int g = 0; g < CPB; g++) {
        int cnt = min(s_cnt[g], CAP);
        int m = m0 + g;
        for (int c = tid; c < cnt; c += 256) {
            float d = cd[g][c]; int i = ci[g][c];
            int rank = 0;
            for (int j = 0; j < cnt; j++) {
                float dj = cd[g][j];
                rank += (dj < d) || (dj == d && ci[g][j] < i);
            }
            if (rank < KNB) g_nbr[m*KNB + rank] = i;
        }
        int v = min(cnt, KNB);
        if (tid == 0) g_cnt[m] = v;
        if (tid >= v && tid < KNB) g_nbr[m*KNB + tid] = 0;
    }
}

// ---------------- per-point nearest center ----------------
__global__ __launch_bounds__(256) void k_nearest() {
    __shared__ float4 sc[CCH];
    const int tid = threadIdx.x;
    const int nb = blockIdx.x * 1024 + tid;
    const int base = blockIdx.y * CCH;
    for (int j = tid; j < CCH; j += 256)
        sc[j] = g_pts[g_idxc[base + j]];
    float4 p0 = g_pts[nb], p1 = g_pts[nb+256], p2 = g_pts[nb+512], p3 = g_pts[nb+768];
    __syncthreads();
    float b0 = 3.4e38f, b1 = 3.4e38f, b2 = 3.4e38f, b3 = 3.4e38f;
    int i0 = 0, i1 = 0, i2 = 0, i3 = 0;
    #pragma unroll 4
    for (int j = 0; j < CCH; j++) {
        float4 c = sc[j];
        float d0 = fmaf(-2.f, fmaf(c.x, p0.x, fmaf(c.y, p0.y, c.z*p0.z)), c.w);
        float d1 = fmaf(-2.f, fmaf(c.x, p1.x, fmaf(c.y, p1.y, c.z*p1.z)), c.w);
        float d2 = fmaf(-2.f, fmaf(c.x, p2.x, fmaf(c.y, p2.y, c.z*p2.z)), c.w);
        float d3 = fmaf(-2.f, fmaf(c.x, p3.x, fmaf(c.y, p3.y, c.z*p3.z)), c.w);
        if (d0 < b0) { b0 = d0; i0 = j; }
        if (d1 < b1) { b1 = d1; i1 = j; }
        if (d2 < b2) { b2 = d2; i2 = j; }
        if (d3 < b3) { b3 = d3; i3 = j; }
    }
    unsigned long long k0 = ((unsigned long long)__float_as_uint(fmaxf(b0 + p0.w, 0.f)) << 32) | (unsigned)(base + i0);
    unsigned long long k1 = ((unsigned long long)__float_as_uint(fmaxf(b1 + p1.w, 0.f)) << 32) | (unsigned)(base + i1);
    unsigned long long k2 = ((unsigned long long)__float_as_uint(fmaxf(b2 + p2.w, 0.f)) << 32) | (unsigned)(base + i2);
    unsigned long long k3 = ((unsigned long long)__float_as_uint(fmaxf(b3 + p3.w, 0.f)) << 32) | (unsigned)(base + i3);
    atomicMin(&g_nearKey[nb],     k0);
    atomicMin(&g_nearKey[nb+256], k1);
    atomicMin(&g_nearKey[nb+512], k2);
    atomicMin(&g_nearKey[nb+768], k3);
}

// ---------------- TF32 tensor-core GEMM (+optional fused LN+residual) --------
__device__ __forceinline__ uint32_t cvt_tf32(float x) {
    uint32_t r;
    asm("cvt.rna.tf32.f32 %0, %1;" : "=r"(r) : "f"(x));
    return r;
}

// LNMODE: 0 = plain epilogue (bias/relu); 1 = bias -> LayerNorm(g,b) + residual
template<int BM, int BN, int WM, int WN, int LNMODE>
__device__ __forceinline__ void gemm_body(
    const float* __restrict__ A, const float* __restrict__ W,
    const float* __restrict__ bias, float* __restrict__ C,
    int Cin, int Cout, int relu,
    const float* __restrict__ lng, const float* __restrict__ lnb,
    const float* __restrict__ resid, int gatherResid)
{
    constexpr int BK = 32;
    constexpr int MT = WM / 16, NT = WN / 8;
    constexpr int WCOLS = BN / WN;
    constexpr int ABYTES = BM * (BK + 4) * 4;
    constexpr int WBYTES = BN * (BK + 4) * 4;
    constexpr int CSBYTES = LNMODE ? BM * (BN + 4) * 4 : 0;
    constexpr int SMEMB = (ABYTES + WBYTES) > CSBYTES ? (ABYTES + WBYTES) : CSBYTES;
    __shared__ __align__(16) char sraw[SMEMB];
    uint32_t (*As)[BK + 4] = reinterpret_cast<uint32_t(*)[BK + 4]>(sraw);
    uint32_t (*Ws)[BK + 4] = reinterpret_cast<uint32_t(*)[BK + 4]>(sraw + ABYTES);

    const int tid = threadIdx.x;
    const int wid = tid >> 5, lane = tid & 31;
    const int wmBase = (wid / WCOLS) * WM;
    const int wnBase = (wid % WCOLS) * WN;
    const int rowBase = blockIdx.x * BM;
    const int colBase = blockIdx.y * BN;
    const int lr = lane >> 2, lc = lane & 3;

    float acc[MT][NT][4];
    #pragma unroll
    for (int i = 0; i < MT; i++)
        #pragma unroll
        for (int j = 0; j < NT; j++)
            #pragma unroll
            for (int q = 0; q < 4; q++) acc[i][j][q] = 0.f;

    for (int k0 = 0; k0 < Cin; k0 += BK) {
        #pragma unroll
        for (int f = tid; f < BM * (BK/4); f += 256) {
            int row = f >> 3, kq = f & 7;
            float4 v = *reinterpret_cast<const float4*>(A + (size_t)(rowBase + row)*Cin + k0 + kq*4);
            uint4 u = make_uint4(cvt_tf32(v.x), cvt_tf32(v.y), cvt_tf32(v.z), cvt_tf32(v.w));
            *reinterpret_cast<uint4*>(&As[row][kq*4]) = u;
        }
        #pragma unroll
        for (int f = tid; f < BN * (BK/4); f += 256) {
            int row = f >> 3, kq = f & 7;
            float4 v = *reinterpret_cast<const float4*>(W + (size_t)(colBase + row)*Cin + k0 + kq*4);
            uint4 u = make_uint4(cvt_tf32(v.x), cvt_tf32(v.y), cvt_tf32(v.z), cvt_tf32(v.w));
            *reinterpret_cast<uint4*>(&Ws[row][kq*4]) = u;
        }
        __syncthreads();

        #pragma unroll
        for (int ks = 0; ks < BK/8; ks++) {
            uint32_t bfr[NT][2];
            #pragma unroll
            for (int nt = 0; nt < NT; nt++) {
                int nn = wnBase + nt*8 + lr;
                bfr[nt][0] = Ws[nn][ks*8 + lc];
                bfr[nt][1] = Ws[nn][ks*8 + lc + 4];
            }
            uint32_t afr[MT][4];
            #pragma unroll
            for (int mt = 0; mt < MT; mt++) {
                int rr = wmBase + mt*16 + lr;
                afr[mt][0] = As[rr][ks*8 + lc];
                afr[mt][1] = As[rr + 8][ks*8 + lc];
                afr[mt][2] = As[rr][ks*8 + lc + 4];
                afr[mt][3] = As[rr + 8][ks*8 + lc + 4];
            }
            #pragma unroll
            for (int mt = 0; mt < MT; mt++)
                #pragma unroll
                for (int nt = 0; nt < NT; nt++) {
                    asm volatile(
                        "mma.sync.aligned.m16n8k8.row.col.f32.tf32.tf32.f32 "
                        "{%0,%1,%2,%3}, {%4,%5,%6,%7}, {%8,%9}, {%0,%1,%2,%3};\n"
                        : "+f"(acc[mt][nt][0]), "+f"(acc[mt][nt][1]),
                          "+f"(acc[mt][nt][2]), "+f"(acc[mt][nt][3])
                        : "r"(afr[mt][0]), "r"(afr[mt][1]), "r"(afr[mt][2]), "r"(afr[mt][3]),
                          "r"(bfr[nt][0]), "r"(bfr[nt][1]));
                }
        }
        __syncthreads();
    }

    if (LNMODE == 0) {
        #pragma unroll
        for (int mt = 0; mt < MT; mt++) {
            #pragma unroll
            for (int nt = 0; nt < NT; nt++) {
                int row0 = rowBase + wmBase + mt*16 + lr;
                int col  = colBase + wnBase + nt*8 + 2*lc;
                float bx = 0.f, by = 0.f;
                if (bias) { bx = bias[col]; by = bias[col+1]; }
                float2 o0 = make_float2(acc[mt][nt][0] + bx, acc[mt][nt][1] + by);
                float2 o1 = make_float2(acc[mt][nt][2] + bx, acc[mt][nt][3] + by);
                if (relu) {
                    o0.x = fmaxf(o0.x, 0.f); o0.y = fmaxf(o0.y, 0.f);
                    o1.x = fmaxf(o1.x, 0.f); o1.y = fmaxf(o1.y, 0.f);
                }
                *reinterpret_cast<float2*>(C + (size_t)row0*Cout + col) = o0;
                *reinterpret_cast<float2*>(C + (size_t)(row0+8)*Cout + col) = o1;
            }
        }
    } else {
        // stage accumulators (with bias) to smem, then per-row LN + residual
        float (*Cs)[BN + 4] = reinterpret_cast<float(*)[BN + 4]>(sraw);
        #pragma unroll
        for (int mt = 0; mt < MT; mt++) {
            #pragma unroll
            for (int nt = 0; nt < NT; nt++) {
                int r0 = wmBase + mt*16 + lr;
                int col = wnBase + nt*8 + 2*lc;
                float bx = bias[col], by = bias[col+1];
                *reinterpret_cast<float2*>(&Cs[r0][col]) =
                    make_float2(acc[mt][nt][0] + bx, acc[mt][nt][1] + by);
                *reinterpret_cast<float2*>(&Cs[r0 + 8][col]) =
                    make_float2(acc[mt][nt][2] + bx, acc[mt][nt][3] + by);
            }
        }
        __syncthreads();
        // 8 warps x (BM/8) rows each; 32 lanes x 4 cols = 128
        #pragma unroll
        for (int r = 0; r < BM/8; r++) {
            int row = wid * (BM/8) + r;
            float4 v = *reinterpret_cast<float4*>(&Cs[row][lane*4]);
            float s = v.x + v.y + v.z + v.w;
            float q = v.x*v.x + v.y*v.y + v.z*v.z + v.w*v.w;
            #pragma unroll
            for (int o = 16; o > 0; o >>= 1) {
                s += __shfl_xor_sync(0xffffffffu, s, o);
                q += __shfl_xor_sync(0xffffffffu, q, o);
            }
            float mu = s * (1.f/DIMF);
            float var = fmaxf(q * (1.f/DIMF) - mu*mu, 0.f);
            float rstd = rsqrtf(var + 1e-5f);
            int grow = rowBase + row;
            int rrow = gatherResid ? g_idxc[grow] : grow;
            float4 gv = *reinterpret_cast<const float4*>(lng + lane*4);
            float4 bv = *reinterpret_cast<const float4*>(lnb + lane*4);
            float4 rv = *reinterpret_cast<const float4*>(resid + (size_t)rrow*DIMF + lane*4);
            float4 o;
            o.x = (v.x - mu) * rstd * gv.x + bv.x + rv.x;
            o.y = (v.y - mu) * rstd * gv.y + bv.y + rv.y;
            o.z = (v.z - mu) * rstd * gv.z + bv.z + rv.z;
            o.w = (v.w - mu) * rstd * gv.w + bv.w + rv.w;
            *reinterpret_cast<float4*>(C + (size_t)grow*DIMF + lane*4) = o;
        }
    }
}

template<int BM, int BN, int WM, int WN>
__global__ __launch_bounds__(256, 2) void k_gemm(
    const float* __restrict__ A, const float* __restrict__ W,
    const float* __restrict__ bias, float* __restrict__ C,
    int Cin, int Cout, int relu)
{
    gemm_body<BM, BN, WM, WN, 0>(A, W, bias, C, Cin, Cout, relu,
                                 nullptr, nullptr, nullptr, 0);
}

template<int BM, int BN, int WM, int WN>
__global__ __launch_bounds__(256, 2) void k_gemm_ln(
    const float* __restrict__ A, const float* __restrict__ W,
    const float* __restrict__ bias, float* __restrict__ C, int Cin,
    const float* __restrict__ lng, const float* __restrict__ lnb,
    const float* __restrict__ resid, int gatherResid)
{
    gemm_body<BM, BN, WM, WN, 1>(A, W, bias, C, Cin, DIMF, 0,
                                 lng, lnb, resid, gatherResid);
}

struct P3 { const float* W[3]; float* C[3]; };
__global__ __launch_bounds__(256, 2) void k_gemm_qkv(const float* __restrict__ A, P3 p)
{
    gemm_body<128, 128, 64, 32, 0>(A, p.W[blockIdx.z], nullptr, p.C[blockIdx.z],
                                   DIMF, DIMF, 0, nullptr, nullptr, nullptr, 0);
}

// ---------------- per-center attention (single gather pass, shuffle softmax) --
__global__ void k_attn() {
    __shared__ float q[DIMF];
    __shared__ float kS[KNB][DIMF + 4];
    __shared__ float vS[KNB][DIMF + 4];
    __shared__ int nbr_s[KNB];
    __shared__ int s_cnt;
    const int m = blockIdx.x, tid = threadIdx.x;
    if (tid < KNB) nbr_s[tid] = g_nbr[m*KNB + tid];
    if (tid == 0) s_cnt = g_cnt[m];
    int ic = g_idxc[m];
    q[tid] = g_Qp[(size_t)ic*DIMF + tid] * 0.17677669529663687f;  // DH^-0.5
    __syncthreads();

    // gather K and V rows in one pass (double MLP)
    #pragma unroll
    for (int f = tid; f < KNB * (DIMF/4); f += 128) {
        int s = f >> 5, c4 = f & 31;
        size_t off = (size_t)nbr_s[s]*DIMF + c4*4;
        float4 kx = *reinterpret_cast<const float4*>(&g_Kp[off]);
        float4 vx = *reinterpret_cast<const float4*>(&g_Vp[off]);
        *reinterpret_cast<float4*>(&kS[s][c4*4]) = kx;
        *reinterpret_cast<float4*>(&vS[s][c4*4]) = vx;
    }
    __syncthreads();

    const int h = tid >> 5, lane = tid & 31;
    const int cnt = s_cnt;
    float logit = -1e9f;
    if (lane < cnt) {
        float a = 0.f;
        #pragma unroll
        for (int d = 0; d < DH; d++) a += q[h*DH + d] * kS[lane][h*DH + d];
        logit = a;
    }
    float mx = logit;
    #pragma unroll
    for (int o = 16; o > 0; o >>= 1) mx = fmaxf(mx, __shfl_xor_sync(0xffffffffu, mx, o));
    float e = (lane < cnt) ? expf(logit - mx) : 0.f;
    float sm = e;
    #pragma unroll
    for (int o = 16; o > 0; o >>= 1) sm += __shfl_xor_sync(0xffffffffu, sm, o);
    float w = e / sm;

    float acc = 0.f;
    #pragma unroll
    for (int kk = 0; kk < KNB; kk++)
        acc += __shfl_sync(0xffffffffu, w, kk) * vS[kk][h*DH + lane];
    g_ao[(size_t)m*DIMF + lane*NH + h] = acc;   // transpose(0,2,1) layout
}

// ---------------- final scatter: out = feats + c2[nearest] ----------------
__global__ void k_scatter(const float* __restrict__ feats, float* __restrict__ out) {
    int i = blockIdx.x * 256 + threadIdx.x;
    int n = i >> 5, c4 = i & 31;
    int ctr = (int)(g_nearKey[n] & 0xffffffffu);
    float4 f = *reinterpret_cast<const float4*>(feats + (size_t)n*DIMF + c4*4);
    float4 c = *reinterpret_cast<const float4*>(g_c2 + (size_t)ctr*DIMF + c4*4);
    f.x += c.x; f.y += c.y; f.z += c.z; f.w += c.w;
    *reinterpret_cast<float4*>(out + (size_t)n*DIMF + c4*4) = f;
}

// ---------------- launch (forked-stream graph) ----------------
extern "C" void kernel_launch(void* const* d_in, const int* in_sizes, int n_in,
                              void* d_out, int out_size) {
    const float* xyz   = (const float*)d_in[0];
    const float* feats = (const float*)d_in[1];
    const long long* idxc = (const long long*)d_in[2];
    const float* Wq = (const float*)d_in[3];
    const float* Wk = (const float*)d_in[4];
    const float* Wv = (const float*)d_in[5];
    const float* Wo = (const float*)d_in[6];
    const float* bo = (const float*)d_in[7];
    const float* g1 = (const float*)d_in[8];
    const float* be1 = (const float*)d_in[9];
    const float* g2 = (const float*)d_in[10];
    const float* be2 = (const float*)d_in[11];
    const float* W1 = (const float*)d_in[12];
    const float* b1f = (const float*)d_in[13];
    const float* W2 = (const float*)d_in[14];
    const float* b2f = (const float*)d_in[15];
    float* out = (float*)d_out;

    float *qp, *kp, *vp, *ao, *c1, *hid, *c2;
    cudaGetSymbolAddress((void**)&qp,  g_Qp);
    cudaGetSymbolAddress((void**)&kp,  g_Kp);
    cudaGetSymbolAddress((void**)&vp,  g_Vp);
    cudaGetSymbolAddress((void**)&ao,  g_ao);
    cudaGetSymbolAddress((void**)&c1,  g_c1);
    cudaGetSymbolAddress((void**)&hid, g_hid);
    cudaGetSymbolAddress((void**)&c2,  g_c2);

    static cudaStream_t s1 = nullptr, s2 = nullptr;
    static cudaEvent_t eFork = nullptr, eTopk = nullptr, eNear = nullptr;
    if (!s1) {
        cudaStreamCreateWithFlags(&s1, cudaStreamNonBlocking);
        cudaStreamCreateWithFlags(&s2, cudaStreamNonBlocking);
        cudaEventCreateWithFlags(&eFork, cudaEventDisableTiming);
        cudaEventCreateWithFlags(&eTopk, cudaEventDisableTiming);
        cudaEventCreateWithFlags(&eNear, cudaEventDisableTiming);
    }
    cudaStream_t s0 = 0;

    k_init<<<NPTS/256, 256, 0, s0>>>(xyz, idxc);
    cudaEventRecord(eFork, s0);

    cudaStreamWaitEvent(s1, eFork, 0);
    cudaStreamWaitEvent(s2, eFork, 0);
    k_topk<<<MC/CPB, 256, 0, s1>>>();
    cudaEventRecord(eTopk, s1);
    k_nearest<<<dim3(NPTS/1024, MC/CCH), 256, 0, s2>>>();
    cudaEventRecord(eNear, s2);

    P3 p;
    p.W[0] = Wq; p.W[1] = Wk; p.W[2] = Wv;
    p.C[0] = qp; p.C[1] = kp; p.C[2] = vp;
    k_gemm_qkv<<<dim3(NPTS/128, 1, 3), 256, 0, s0>>>(feats, p);

    cudaStreamWaitEvent(s0, eTopk, 0);
    k_attn<<<MC, 128, 0, s0>>>();

    // Wo GEMM + LN1 + residual(feats gathered by idxc) -> c1
    k_gemm_ln<64,128,32,32><<<dim3(MC/64, 1), 256, 0, s0>>>(
        ao, Wo, bo, c1, DIMF, g1, be1, feats, 1);
    // FFN up (relu)
    k_gemm<64,128,32,32><<<dim3(MC/64, HID/128), 256, 0, s0>>>(
        c1, W1, b1f, hid, DIMF, HID, 1);
    // FFN down + LN2 + residual(c1) -> c2
    k_gemm_ln<64,128,32,32><<<dim3(MC/64, 1), 256, 0, s0>>>(
        hid, W2, b2f, c2, HID, g2, be2, c1, 0);

    cudaStreamWaitEvent(s0, eNear, 0);
    k_scatter<<<NPTS*(DIMF/4)/256, 256, 0, s0>>>(feats, out);
}

// round 6
// speedup vs baseline: 1.1421x; 1.1421x over previous
#include <cuda_runtime.h>
#include <math.h>
#include <stdint.h>

#define NPTS 16384
#define MC   4096
#define DIMF 128
#define NH   4
#define DH   32
#define KNB  32
#define HID  512
#define RAD  0.3f
#define R2L  0.09000902f
#define CAP  512
#define CPB  8
#define CCH  512

// ---------------- scratch ----------------
__device__ int    g_idxc[MC];
__device__ float4 g_pts[NPTS];
__device__ __align__(16) float g_Qp[NPTS*DIMF];
__device__ __align__(16) float g_Kp[NPTS*DIMF];
__device__ __align__(16) float g_Vp[NPTS*DIMF];
__device__ int    g_nbr[MC*KNB];
__device__ int    g_cnt[MC];
__device__ unsigned long long g_nearKey[NPTS];
__device__ __align__(16) float g_ao[MC*DIMF];
__device__ __align__(16) float g_c1[MC*DIMF];
__device__ __align__(16) float g_hid[MC*HID];
__device__ __align__(16) float g_c2[MC*DIMF];

// ---------------- init: pack points + nearKey + idx dtype convert ----------------
__global__ void k_init(const float* __restrict__ xyz, const long long* __restrict__ raw) {
    int n = blockIdx.x * 256 + threadIdx.x;
    float x = xyz[3*n], y = xyz[3*n+1], z = xyz[3*n+2];
    g_pts[n] = make_float4(x, y, z, x*x + y*y + z*z);
    g_nearKey[n] = ~0ull;
    if (blockIdx.x == 0) {
        __shared__ int s_ok;
        if (threadIdx.x == 0) s_ok = 1;
        __syncthreads();
        for (int m = threadIdx.x; m < MC/2; m += 256) {
            long long v = raw[m];
            if (v < 0 || v >= NPTS) s_ok = 0;
        }
        __syncthreads();
        if (s_ok) {
            for (int m = threadIdx.x; m < MC; m += 256)
                g_idxc[m] = (int)raw[m];
        } else {
            const int* r32 = (const int*)raw;
            for (int m = threadIdx.x; m < MC; m += 256)
                g_idxc[m] = r32[m];
        }
    }
}

// ---------------- per-center radius filter + exact top-K by rank ----------------
__global__ __launch_bounds__(256) void k_topk() {
    __shared__ float cd[CPB][CAP];
    __shared__ int   ci[CPB][CAP];
    __shared__ int   s_cnt[CPB];
    const int tid = threadIdx.x;
    const int m0 = blockIdx.x * CPB;
    if (tid < CPB) s_cnt[tid] = 0;
    __syncthreads();

    float cx2[CPB], cy2[CPB], cz2[CPB], cc[CPB];
    #pragma unroll
    for (int g = 0; g < CPB; g++) {
        float4 c = g_pts[g_idxc[m0 + g]];
        cx2[g] = -2.f*c.x; cy2[g] = -2.f*c.y; cz2[g] = -2.f*c.z; cc[g] = c.w;
    }
    __syncthreads();

    for (int n = tid; n < NPTS; n += 256) {
        float4 p = g_pts[n];
        float rhs = R2L - p.w;
        #pragma unroll
        for (int g = 0; g < CPB; g++) {
            float t = fmaf(cx2[g], p.x, cc[g]);
            t = fmaf(cy2[g], p.y, t);
            t = fmaf(cz2[g], p.z, t);
            if (t < rhs) {
                float dist = sqrtf(fmaxf(t + p.w, 1e-12f));
                if (dist < RAD) {
                    int q = atomicAdd(&s_cnt[g], 1);
                    if (q < CAP) { cd[g][q] = dist; ci[g][q] = n; }
                }
            }
        }
    }
    __syncthreads();

    #pragma unroll
    for (int g = 0; g < CPB; g++) {
        int cnt = min(s_cnt[g], CAP);
        int m = m0 + g;
        for (int c = tid; c < cnt; c += 256) {
            float d = cd[g][c]; int i = ci[g][c];
            int rank = 0;
            for (int j = 0; j < cnt; j++) {
                float dj = cd[g][j];
                rank += (dj < d) || (dj == d && ci[g][j] < i);
            }
            if (rank < KNB) g_nbr[m*KNB + rank] = i;
        }
        int v = min(cnt, KNB);
        if (tid == 0) g_cnt[m] = v;
        if (tid >= v && tid < KNB) g_nbr[m*KNB + tid] = 0;
    }
}

// ---------------- per-point nearest center ----------------
__global__ __launch_bounds__(256) void k_nearest() {
    __shared__ float4 sc[CCH];
    const int tid = threadIdx.x;
    const int nb = blockIdx.x * 1024 + tid;
    const int base = blockIdx.y * CCH;
    for (int j = tid; j < CCH; j += 256)
        sc[j] = g_pts[g_idxc[base + j]];
    float4 p0 = g_pts[nb], p1 = g_pts[nb+256], p2 = g_pts[nb+512], p3 = g_pts[nb+768];
    __syncthreads();
    float b0 = 3.4e38f, b1 = 3.4e38f, b2 = 3.4e38f, b3 = 3.4e38f;
    int i0 = 0, i1 = 0, i2 = 0, i3 = 0;
    #pragma unroll 4
    for (int j = 0; j < CCH; j++) {
        float4 c = sc[j];
        float d0 = fmaf(-2.f, fmaf(c.x, p0.x, fmaf(c.y, p0.y, c.z*p0.z)), c.w);
        float d1 = fmaf(-2.f, fmaf(c.x, p1.x, fmaf(c.y, p1.y, c.z*p1.z)), c.w);
        float d2 = fmaf(-2.f, fmaf(c.x, p2.x, fmaf(c.y, p2.y, c.z*p2.z)), c.w);
        float d3 = fmaf(-2.f, fmaf(c.x, p3.x, fmaf(c.y, p3.y, c.z*p3.z)), c.w);
        if (d0 < b0) { b0 = d0; i0 = j; }
        if (d1 < b1) { b1 = d1; i1 = j; }
        if (d2 < b2) { b2 = d2; i2 = j; }
        if (d3 < b3) { b3 = d3; i3 = j; }
    }
    unsigned long long k0 = ((unsigned long long)__float_as_uint(fmaxf(b0 + p0.w, 0.f)) << 32) | (unsigned)(base + i0);
    unsigned long long k1 = ((unsigned long long)__float_as_uint(fmaxf(b1 + p1.w, 0.f)) << 32) | (unsigned)(base + i1);
    unsigned long long k2 = ((unsigned long long)__float_as_uint(fmaxf(b2 + p2.w, 0.f)) << 32) | (unsigned)(base + i2);
    unsigned long long k3 = ((unsigned long long)__float_as_uint(fmaxf(b3 + p3.w, 0.f)) << 32) | (unsigned)(base + i3);
    atomicMin(&g_nearKey[nb],     k0);
    atomicMin(&g_nearKey[nb+256], k1);
    atomicMin(&g_nearKey[nb+512], k2);
    atomicMin(&g_nearKey[nb+768], k3);
}

// ---------------- TF32 GEMM: cp.async double-buffered pipeline ----------------
__device__ __forceinline__ uint32_t cvt_tf32(float x) {
    uint32_t r;
    asm("cvt.rna.tf32.f32 %0, %1;" : "=r"(r) : "f"(x));
    return r;
}
__device__ __forceinline__ uint32_t smem_u32(const void* p) {
    return (uint32_t)__cvta_generic_to_shared(p);
}
__device__ __forceinline__ void cp_async16(uint32_t dst, const float* src) {
    asm volatile("cp.async.cg.shared.global [%0], [%1], 16;\n" :: "r"(dst), "l"(src));
}
__device__ __forceinline__ void cp_commit() { asm volatile("cp.async.commit_group;\n"); }
template<int N> __device__ __forceinline__ void cp_wait() {
    asm volatile("cp.async.wait_group %0;\n" :: "n"(N));
}

// LNMODE: 0 = bias/relu epilogue; 1 = bias -> LayerNorm + residual
template<int BM, int BN, int WM, int WN, int LNMODE>
__device__ __forceinline__ void gemm_body(
    const float* __restrict__ A, const float* __restrict__ W,
    const float* __restrict__ bias, float* __restrict__ C,
    int Cin, int Cout, int relu,
    const float* __restrict__ lng, const float* __restrict__ lnb,
    const float* __restrict__ resid, int gatherResid)
{
    constexpr int BK = 16;
    constexpr int LDK = BK + 4;             // 20 floats = 80B row: conflict-free frags
    constexpr int MT = WM / 16, NT = WN / 8;
    constexpr int WCOLS = BN / WN;
    extern __shared__ __align__(16) char dsm[];
    float (*As)[BM][LDK] = reinterpret_cast<float(*)[BM][LDK]>(dsm);
    float (*Ws)[BN][LDK] = reinterpret_cast<float(*)[BN][LDK]>(dsm + 2*BM*LDK*sizeof(float));

    const int tid = threadIdx.x;
    const int wid = tid >> 5, lane = tid & 31;
    const int wmBase = (wid / WCOLS) * WM;
    const int wnBase = (wid % WCOLS) * WN;
    const int rowBase = blockIdx.x * BM;
    const int colBase = blockIdx.y * BN;
    const int lr = lane >> 2, lc = lane & 3;

    float acc[MT][NT][4];
    #pragma unroll
    for (int i = 0; i < MT; i++)
        #pragma unroll
        for (int j = 0; j < NT; j++)
            #pragma unroll
            for (int q = 0; q < 4; q++) acc[i][j][q] = 0.f;

    auto copy_tile = [&](int st, int k0) {
        #pragma unroll
        for (int f = tid; f < BM * (BK/4); f += 256) {
            int row = f >> 2, kq = f & 3;
            cp_async16(smem_u32(&As[st][row][kq*4]),
                       A + (size_t)(rowBase + row)*Cin + k0 + kq*4);
        }
        #pragma unroll
        for (int f = tid; f < BN * (BK/4); f += 256) {
            int row = f >> 2, kq = f & 3;
            cp_async16(smem_u32(&Ws[st][row][kq*4]),
                       W + (size_t)(colBase + row)*Cin + k0 + kq*4);
        }
    };

    const int NTILES = Cin / BK;
    copy_tile(0, 0);
    cp_commit();

    for (int t = 0; t < NTILES; t++) {
        const int st = t & 1;
        if (t + 1 < NTILES) { copy_tile(st ^ 1, (t+1)*BK); cp_commit(); cp_wait<1>(); }
        else cp_wait<0>();
        __syncthreads();

        #pragma unroll
        for (int ks = 0; ks < BK/8; ks++) {
            uint32_t bfr[NT][2];
            #pragma unroll
            for (int nt = 0; nt < NT; nt++) {
                int nn = wnBase + nt*8 + lr;
                bfr[nt][0] = cvt_tf32(Ws[st][nn][ks*8 + lc]);
                bfr[nt][1] = cvt_tf32(Ws[st][nn][ks*8 + lc + 4]);
            }
            uint32_t afr[MT][4];
            #pragma unroll
            for (int mt = 0; mt < MT; mt++) {
                int rr = wmBase + mt*16 + lr;
                afr[mt][0] = cvt_tf32(As[st][rr][ks*8 + lc]);
                afr[mt][1] = cvt_tf32(As[st][rr + 8][ks*8 + lc]);
                afr[mt][2] = cvt_tf32(As[st][rr][ks*8 + lc + 4]);
                afr[mt][3] = cvt_tf32(As[st][rr + 8][ks*8 + lc + 4]);
            }
            #pragma unroll
            for (int mt = 0; mt < MT; mt++)
                #pragma unroll
                for (int nt = 0; nt < NT; nt++) {
                    asm volatile(
                        "mma.sync.aligned.m16n8k8.row.col.f32.tf32.tf32.f32 "
                        "{%0,%1,%2,%3}, {%4,%5,%6,%7}, {%8,%9}, {%0,%1,%2,%3};\n"
                        : "+f"(acc[mt][nt][0]), "+f"(acc[mt][nt][1]),
                          "+f"(acc[mt][nt][2]), "+f"(acc[mt][nt][3])
                        : "r"(afr[mt][0]), "r"(afr[mt][1]), "r"(afr[mt][2]), "r"(afr[mt][3]),
                          "r"(bfr[nt][0]), "r"(bfr[nt][1]));
                }
        }
        __syncthreads();
    }

    if (LNMODE == 0) {
        #pragma unroll
        for (int mt = 0; mt < MT; mt++) {
            #pragma unroll
            for (int nt = 0; nt < NT; nt++) {
                int row0 = rowBase + wmBase + mt*16 + lr;
                int col  = colBase + wnBase + nt*8 + 2*lc;
                float bx = 0.f, by = 0.f;
                if (bias) { bx = bias[col]; by = bias[col+1]; }
                float2 o0 = make_float2(acc[mt][nt][0] + bx, acc[mt][nt][1] + by);
                float2 o1 = make_float2(acc[mt][nt][2] + bx, acc[mt][nt][3] + by);
                if (relu) {
                    o0.x = fmaxf(o0.x, 0.f); o0.y = fmaxf(o0.y, 0.f);
                    o1.x = fmaxf(o1.x, 0.f); o1.y = fmaxf(o1.y, 0.f);
                }
                *reinterpret_cast<float2*>(C + (size_t)row0*Cout + col) = o0;
                *reinterpret_cast<float2*>(C + (size_t)(row0+8)*Cout + col) = o1;
            }
        }
    } else {
        float (*Cs)[BN + 4] = reinterpret_cast<float(*)[BN + 4]>(dsm);
        #pragma unroll
        for (int mt = 0; mt < MT; mt++) {
            #pragma unroll
            for (int nt = 0; nt < NT; nt++) {
                int r0 = wmBase + mt*16 + lr;
                int col = wnBase + nt*8 + 2*lc;
                float bx = bias[col], by = bias[col+1];
                *reinterpret_cast<float2*>(&Cs[r0][col]) =
                    make_float2(acc[mt][nt][0] + bx, acc[mt][nt][1] + by);
                *reinterpret_cast<float2*>(&Cs[r0 + 8][col]) =
                    make_float2(acc[mt][nt][2] + bx, acc[mt][nt][3] + by);
            }
        }
        __syncthreads();
        #pragma unroll
        for (int r = 0; r < BM/8; r++) {
            int row = wid * (BM/8) + r;
            float4 v = *reinterpret_cast<float4*>(&Cs[row][lane*4]);
            float s = v.x + v.y + v.z + v.w;
            float q = v.x*v.x + v.y*v.y + v.z*v.z + v.w*v.w;
            #pragma unroll
            for (int o = 16; o > 0; o >>= 1) {
                s += __shfl_xor_sync(0xffffffffu, s, o);
                q += __shfl_xor_sync(0xffffffffu, q, o);
            }
            float mu = s * (1.f/DIMF);
            float var = fmaxf(q * (1.f/DIMF) - mu*mu, 0.f);
            float rstd = rsqrtf(var + 1e-5f);
            int grow = rowBase + row;
            int rrow = gatherResid ? g_idxc[grow] : grow;
            float4 gv = *reinterpret_cast<const float4*>(lng + lane*4);
            float4 bv = *reinterpret_cast<const float4*>(lnb + lane*4);
            float4 rv = *reinterpret_cast<const float4*>(resid + (size_t)rrow*DIMF + lane*4);
            float4 o;
            o.x = (v.x - mu) * rstd * gv.x + bv.x + rv.x;
            o.y = (v.y - mu) * rstd * gv.y + bv.y + rv.y;
            o.z = (v.z - mu) * rstd * gv.z + bv.z + rv.z;
            o.w = (v.w - mu) * rstd * gv.w + bv.w + rv.w;
            *reinterpret_cast<float4*>(C + (size_t)grow*DIMF + lane*4) = o;
        }
    }
}

template<int BM, int BN, int WM, int WN>
__global__ __launch_bounds__(256, 2) void k_gemm(
    const float* __restrict__ A, const float* __restrict__ W,
    const float* __restrict__ bias, float* __restrict__ C,
    int Cin, int Cout, int relu)
{
    gemm_body<BM, BN, WM, WN, 0>(A, W, bias, C, Cin, Cout, relu,
                                 nullptr, nullptr, nullptr, 0);
}

template<int BM, int BN, int WM, int WN>
__global__ __launch_bounds__(256, 2) void k_gemm_ln(
    const float* __restrict__ A, const float* __restrict__ W,
    const float* __restrict__ bias, float* __restrict__ C, int Cin,
    const float* __restrict__ lng, const float* __restrict__ lnb,
    const float* __restrict__ resid, int gatherResid)
{
    gemm_body<BM, BN, WM, WN, 1>(A, W, bias, C, Cin, DIMF, 0,
                                 lng, lnb, resid, gatherResid);
}

struct P3 { const float* W[3]; float* C[3]; };
__global__ __launch_bounds__(256, 2) void k_gemm_qkv(const float* __restrict__ A, P3 p)
{
    gemm_body<128, 128, 64, 32, 0>(A, p.W[blockIdx.z], nullptr, p.C[blockIdx.z],
                                   DIMF, DIMF, 0, nullptr, nullptr, nullptr, 0);
}

// smem byte counts (BK=16 pipeline, 2 stages)
#define GSM(BM_, BN_) (2 * ((BM_) + (BN_)) * 20 * 4)
#define LNSM(BM_, BN_) ((BM_) * ((BN_) + 4) * 4)
static const int SM_QKV = GSM(128,128);                                   // 81920
static const int SM_W1  = GSM(64,128);                                    // 61440
static const int SM_LN  = GSM(32,128) > LNSM(32,128) ? GSM(32,128) : LNSM(32,128); // 25600

// ---------------- per-center attention (single gather pass, shuffle softmax) --
__global__ void k_attn() {
    __shared__ float q[DIMF];
    __shared__ float kS[KNB][DIMF + 4];
    __shared__ float vS[KNB][DIMF + 4];
    __shared__ int nbr_s[KNB];
    __shared__ int s_cnt;
    const int m = blockIdx.x, tid = threadIdx.x;
    if (tid < KNB) nbr_s[tid] = g_nbr[m*KNB + tid];
    if (tid == 0) s_cnt = g_cnt[m];
    int ic = g_idxc[m];
    q[tid] = g_Qp[(size_t)ic*DIMF + tid] * 0.17677669529663687f;  // DH^-0.5
    __syncthreads();

    #pragma unroll
    for (int f = tid; f < KNB * (DIMF/4); f += 128) {
        int s = f >> 5, c4 = f & 31;
        size_t off = (size_t)nbr_s[s]*DIMF + c4*4;
        float4 kx = *reinterpret_cast<const float4*>(&g_Kp[off]);
        float4 vx = *reinterpret_cast<const float4*>(&g_Vp[off]);
        *reinterpret_cast<float4*>(&kS[s][c4*4]) = kx;
        *reinterpret_cast<float4*>(&vS[s][c4*4]) = vx;
    }
    __syncthreads();

    const int h = tid >> 5, lane = tid & 31;
    const int cnt = s_cnt;
    float logit = -1e9f;
    if (lane < cnt) {
        float a = 0.f;
        #pragma unroll
        for (int d = 0; d < DH; d++) a += q[h*DH + d] * kS[lane][h*DH + d];
        logit = a;
    }
    float mx = logit;
    #pragma unroll
    for (int o = 16; o > 0; o >>= 1) mx = fmaxf(mx, __shfl_xor_sync(0xffffffffu, mx, o));
    float e = (lane < cnt) ? expf(logit - mx) : 0.f;
    float sm = e;
    #pragma unroll
    for (int o = 16; o > 0; o >>= 1) sm += __shfl_xor_sync(0xffffffffu, sm, o);
    float w = e / sm;

    float acc = 0.f;
    #pragma unroll
    for (int kk = 0; kk < KNB; kk++)
        acc += __shfl_sync(0xffffffffu, w, kk) * vS[kk][h*DH + lane];
    g_ao[(size_t)m*DIMF + lane*NH + h] = acc;   // transpose(0,2,1) layout
}

// ---------------- final scatter: out = feats + c2[nearest] ----------------
__global__ void k_scatter(const float* __restrict__ feats, float* __restrict__ out) {
    int i = blockIdx.x * 256 + threadIdx.x;
    int n = i >> 5, c4 = i & 31;
    int ctr = (int)(g_nearKey[n] & 0xffffffffu);
    float4 f = *reinterpret_cast<const float4*>(feats + (size_t)n*DIMF + c4*4);
    float4 c = *reinterpret_cast<const float4*>(g_c2 + (size_t)ctr*DIMF + c4*4);
    f.x += c.x; f.y += c.y; f.z += c.z; f.w += c.w;
    *reinterpret_cast<float4*>(out + (size_t)n*DIMF + c4*4) = f;
}

// ---------------- launch (forked-stream graph) ----------------
extern "C" void kernel_launch(void* const* d_in, const int* in_sizes, int n_in,
                              void* d_out, int out_size) {
    const float* xyz   = (const float*)d_in[0];
    const float* feats = (const float*)d_in[1];
    const long long* idxc = (const long long*)d_in[2];
    const float* Wq = (const float*)d_in[3];
    const float* Wk = (const float*)d_in[4];
    const float* Wv = (const float*)d_in[5];
    const float* Wo = (const float*)d_in[6];
    const float* bo = (const float*)d_in[7];
    const float* g1 = (const float*)d_in[8];
    const float* be1 = (const float*)d_in[9];
    const float* g2 = (const float*)d_in[10];
    const float* be2 = (const float*)d_in[11];
    const float* W1 = (const float*)d_in[12];
    const float* b1f = (const float*)d_in[13];
    const float* W2 = (const float*)d_in[14];
    const float* b2f = (const float*)d_in[15];
    float* out = (float*)d_out;

    float *qp, *kp, *vp, *ao, *c1, *hid, *c2;
    cudaGetSymbolAddress((void**)&qp,  g_Qp);
    cudaGetSymbolAddress((void**)&kp,  g_Kp);
    cudaGetSymbolAddress((void**)&vp,  g_Vp);
    cudaGetSymbolAddress((void**)&ao,  g_ao);
    cudaGetSymbolAddress((void**)&c1,  g_c1);
    cudaGetSymbolAddress((void**)&hid, g_hid);
    cudaGetSymbolAddress((void**)&c2,  g_c2);

    static cudaStream_t s1 = nullptr, s2 = nullptr;
    static cudaEvent_t eFork = nullptr, eTopk = nullptr, eNear = nullptr;
    if (!s1) {
        cudaStreamCreateWithFlags(&s1, cudaStreamNonBlocking);
        cudaStreamCreateWithFlags(&s2, cudaStreamNonBlocking);
        cudaEventCreateWithFlags(&eFork, cudaEventDisableTiming);
        cudaEventCreateWithFlags(&eTopk, cudaEventDisableTiming);
        cudaEventCreateWithFlags(&eNear, cudaEventDisableTiming);
        cudaFuncSetAttribute(k_gemm_qkv,
            cudaFuncAttributeMaxDynamicSharedMemorySize, SM_QKV);
        cudaFuncSetAttribute(k_gemm<64,128,32,32>,
            cudaFuncAttributeMaxDynamicSharedMemorySize, SM_W1);
        cudaFuncSetAttribute(k_gemm_ln<32,128,16,32>,
            cudaFuncAttributeMaxDynamicSharedMemorySize, SM_LN);
    }
    cudaStream_t s0 = 0;

    k_init<<<NPTS/256, 256, 0, s0>>>(xyz, idxc);
    cudaEventRecord(eFork, s0);

    cudaStreamWaitEvent(s1, eFork, 0);
    cudaStreamWaitEvent(s2, eFork, 0);
    k_topk<<<MC/CPB, 256, 0, s1>>>();
    cudaEventRecord(eTopk, s1);
    k_nearest<<<dim3(NPTS/1024, MC/CCH), 256, 0, s2>>>();
    cudaEventRecord(eNear, s2);

    P3 p;
    p.W[0] = Wq; p.W[1] = Wk; p.W[2] = Wv;
    p.C[0] = qp; p.C[1] = kp; p.C[2] = vp;
    k_gemm_qkv<<<dim3(NPTS/128, 1, 3), 256, SM_QKV, s0>>>(feats, p);

    cudaStreamWaitEvent(s0, eTopk, 0);
    k_attn<<<MC, 128, 0, s0>>>();

    // Wo GEMM + LN1 + residual(feats gathered by idxc) -> c1   (128 blocks)
    k_gemm_ln<32,128,16,32><<<dim3(MC/32, 1), 256, SM_LN, s0>>>(
        ao, Wo, bo, c1, DIMF, g1, be1, feats, 1);
    // FFN up (relu)   (256 blocks)
    k_gemm<64,128,32,32><<<dim3(MC/64, HID/128), 256, SM_W1, s0>>>(
        c1, W1, b1f, hid, DIMF, HID, 1);
    // FFN down + LN2 + residual(c1) -> c2   (128 blocks)
    k_gemm_ln<32,128,16,32><<<dim3(MC/32, 1), 256, SM_LN, s0>>>(
        hid, W2, b2f, c2, HID, g2, be2, c1, 0);

    cudaStreamWaitEvent(s0, eNear, 0);
    k_scatter<<<NPTS*(DIMF/4)/256, 256, 0, s0>>>(feats, out);
}

// round 7
// speedup vs baseline: 1.1704x; 1.0248x over previous
#include <cuda_runtime.h>
#include <math.h>
#include <stdint.h>

#define NPTS 16384
#define MC   4096
#define DIMF 128
#define NH   4
#define DH   32
#define KNB  32
#define HID  512
#define RAD  0.3f
#define R2L  0.09000902f
#define CAP  512
#define CPB  8
#define CCH  512

// ---------------- scratch ----------------
__device__ int    g_idxc[MC];
__device__ float4 g_pts[NPTS];
__device__ __align__(16) float g_Qc[MC*DIMF];     // Q projected at centers only
__device__ __align__(16) float g_Kp[NPTS*DIMF];
__device__ __align__(16) float g_Vp[NPTS*DIMF];
__device__ int    g_nbr[MC*KNB];
__device__ int    g_cnt[MC];
__device__ unsigned long long g_nearKey[NPTS];
__device__ __align__(16) float g_ao[MC*DIMF];
__device__ __align__(16) float g_c1[MC*DIMF];
__device__ __align__(16) float g_hid[MC*HID];
__device__ __align__(16) float g_c2[MC*DIMF];

// ---------------- init: pack points + nearKey + idx dtype convert ----------------
__global__ void k_init(const float* __restrict__ xyz, const long long* __restrict__ raw) {
    int n = blockIdx.x * 256 + threadIdx.x;
    float x = xyz[3*n], y = xyz[3*n+1], z = xyz[3*n+2];
    g_pts[n] = make_float4(x, y, z, x*x + y*y + z*z);
    g_nearKey[n] = ~0ull;
    if (blockIdx.x == 0) {
        __shared__ int s_ok;
        if (threadIdx.x == 0) s_ok = 1;
        __syncthreads();
        for (int m = threadIdx.x; m < MC/2; m += 256) {
            long long v = raw[m];
            if (v < 0 || v >= NPTS) s_ok = 0;
        }
        __syncthreads();
        if (s_ok) {
            for (int m = threadIdx.x; m < MC; m += 256)
                g_idxc[m] = (int)raw[m];
        } else {
            const int* r32 = (const int*)raw;
            for (int m = threadIdx.x; m < MC; m += 256)
                g_idxc[m] = r32[m];
        }
    }
}

// ---------------- per-center radius filter + exact top-K by rank ----------------
__global__ __launch_bounds__(256) void k_topk() {
    __shared__ float cd[CPB][CAP];
    __shared__ int   ci[CPB][CAP];
    __shared__ int   s_cnt[CPB];
    const int tid = threadIdx.x;
    const int m0 = blockIdx.x * CPB;
    if (tid < CPB) s_cnt[tid] = 0;
    __syncthreads();

    float cx2[CPB], cy2[CPB], cz2[CPB], cc[CPB];
    #pragma unroll
    for (int g = 0; g < CPB; g++) {
        float4 c = g_pts[g_idxc[m0 + g]];
        cx2[g] = -2.f*c.x; cy2[g] = -2.f*c.y; cz2[g] = -2.f*c.z; cc[g] = c.w;
    }
    __syncthreads();

    for (int n = tid; n < NPTS; n += 256) {
        float4 p = g_pts[n];
        float rhs = R2L - p.w;
        #pragma unroll
        for (int g = 0; g < CPB; g++) {
            float t = fmaf(cx2[g], p.x, cc[g]);
            t = fmaf(cy2[g], p.y, t);
            t = fmaf(cz2[g], p.z, t);
            if (t < rhs) {
                float dist = sqrtf(fmaxf(t + p.w, 1e-12f));
                if (dist < RAD) {
                    int q = atomicAdd(&s_cnt[g], 1);
                    if (q < CAP) { cd[g][q] = dist; ci[g][q] = n; }
                }
            }
        }
    }
    __syncthreads();

    #pragma unroll
    for (int g = 0; g < CPB; g++) {
        int cnt = min(s_cnt[g], CAP);
        int m = m0 + g;
        for (int c = tid; c < cnt; c += 256) {
            float d = cd[g][c]; int i = ci[g][c];
            int rank = 0;
            for (int j = 0; j < cnt; j++) {
                float dj = cd[g][j];
                rank += (dj < d) || (dj == d && ci[g][j] < i);
            }
            if (rank < KNB) g_nbr[m*KNB + rank] = i;
        }
        int v = min(cnt, KNB);
        if (tid == 0) g_cnt[m] = v;
        if (tid >= v && tid < KNB) g_nbr[m*KNB + tid] = 0;
    }
}

// ---------------- per-point nearest center ----------------
__global__ __launch_bounds__(256) void k_nearest() {
    __shared__ float4 sc[CCH];
    const int tid = threadIdx.x;
    const int nb = blockIdx.x * 1024 + tid;
    const int base = blockIdx.y * CCH;
    for (int j = tid; j < CCH; j += 256)
        sc[j] = g_pts[g_idxc[base + j]];
    float4 p0 = g_pts[nb], p1 = g_pts[nb+256], p2 = g_pts[nb+512], p3 = g_pts[nb+768];
    __syncthreads();
    float b0 = 3.4e38f, b1 = 3.4e38f, b2 = 3.4e38f, b3 = 3.4e38f;
    int i0 = 0, i1 = 0, i2 = 0, i3 = 0;
    #pragma unroll 4
    for (int j = 0; j < CCH; j++) {
        float4 c = sc[j];
        float d0 = fmaf(-2.f, fmaf(c.x, p0.x, fmaf(c.y, p0.y, c.z*p0.z)), c.w);
        float d1 = fmaf(-2.f, fmaf(c.x, p1.x, fmaf(c.y, p1.y, c.z*p1.z)), c.w);
        float d2 = fmaf(-2.f, fmaf(c.x, p2.x, fmaf(c.y, p2.y, c.z*p2.z)), c.w);
        float d3 = fmaf(-2.f, fmaf(c.x, p3.x, fmaf(c.y, p3.y, c.z*p3.z)), c.w);
        if (d0 < b0) { b0 = d0; i0 = j; }
        if (d1 < b1) { b1 = d1; i1 = j; }
        if (d2 < b2) { b2 = d2; i2 = j; }
        if (d3 < b3) { b3 = d3; i3 = j; }
    }
    unsigned long long k0 = ((unsigned long long)__float_as_uint(fmaxf(b0 + p0.w, 0.f)) << 32) | (unsigned)(base + i0);
    unsigned long long k1 = ((unsigned long long)__float_as_uint(fmaxf(b1 + p1.w, 0.f)) << 32) | (unsigned)(base + i1);
    unsigned long long k2 = ((unsigned long long)__float_as_uint(fmaxf(b2 + p2.w, 0.f)) << 32) | (unsigned)(base + i2);
    unsigned long long k3 = ((unsigned long long)__float_as_uint(fmaxf(b3 + p3.w, 0.f)) << 32) | (unsigned)(base + i3);
    atomicMin(&g_nearKey[nb],     k0);
    atomicMin(&g_nearKey[nb+256], k1);
    atomicMin(&g_nearKey[nb+512], k2);
    atomicMin(&g_nearKey[nb+768], k3);
}

// ---------------- TF32 GEMM: cp.async double-buffered pipeline ----------------
__device__ __forceinline__ uint32_t cvt_tf32(float x) {
    uint32_t r;
    asm("cvt.rna.tf32.f32 %0, %1;" : "=r"(r) : "f"(x));
    return r;
}
__device__ __forceinline__ uint32_t smem_u32(const void* p) {
    return (uint32_t)__cvta_generic_to_shared(p);
}
__device__ __forceinline__ void cp_async16(uint32_t dst, const float* src) {
    asm volatile("cp.async.cg.shared.global [%0], [%1], 16;\n" :: "r"(dst), "l"(src));
}
__device__ __forceinline__ void cp_commit() { asm volatile("cp.async.commit_group;\n"); }
template<int N> __device__ __forceinline__ void cp_wait() {
    asm volatile("cp.async.wait_group %0;\n" :: "n"(N));
}

// LNMODE: 0 = bias/relu epilogue; 1 = bias -> LayerNorm + residual
// GATHERA: A row r comes from A[rowIdx[r]]
template<int BM, int BN, int WM, int WN, int LNMODE, int GATHERA>
__device__ __forceinline__ void gemm_body(
    const float* __restrict__ A, const float* __restrict__ W,
    const float* __restrict__ bias, float* __restrict__ C,
    int Cin, int Cout, int relu,
    const float* __restrict__ lng, const float* __restrict__ lnb,
    const float* __restrict__ resid, int gatherResid,
    const int* __restrict__ rowIdx)
{
    constexpr int BK = 16;
    constexpr int LDK = BK + 4;
    constexpr int MT = WM / 16, NT = WN / 8;
    constexpr int WCOLS = BN / WN;
    extern __shared__ __align__(16) char dsm[];
    float (*As)[BM][LDK] = reinterpret_cast<float(*)[BM][LDK]>(dsm);
    float (*Ws)[BN][LDK] = reinterpret_cast<float(*)[BN][LDK]>(dsm + 2*BM*LDK*sizeof(float));

    const int tid = threadIdx.x;
    const int wid = tid >> 5, lane = tid & 31;
    const int wmBase = (wid / WCOLS) * WM;
    const int wnBase = (wid % WCOLS) * WN;
    const int rowBase = blockIdx.x * BM;
    const int colBase = blockIdx.y * BN;
    const int lr = lane >> 2, lc = lane & 3;

    float acc[MT][NT][4];
    #pragma unroll
    for (int i = 0; i < MT; i++)
        #pragma unroll
        for (int j = 0; j < NT; j++)
            #pragma unroll
            for (int q = 0; q < 4; q++) acc[i][j][q] = 0.f;

    auto copy_tile = [&](int st, int k0) {
        #pragma unroll
        for (int f = tid; f < BM * (BK/4); f += 256) {
            int row = f >> 2, kq = f & 3;
            int ar = GATHERA ? rowIdx[rowBase + row] : (rowBase + row);
            cp_async16(smem_u32(&As[st][row][kq*4]),
                       A + (size_t)ar*Cin + k0 + kq*4);
        }
        #pragma unroll
        for (int f = tid; f < BN * (BK/4); f += 256) {
            int row = f >> 2, kq = f & 3;
            cp_async16(smem_u32(&Ws[st][row][kq*4]),
                       W + (size_t)(colBase + row)*Cin + k0 + kq*4);
        }
    };

    const int NTILES = Cin / BK;
    copy_tile(0, 0);
    cp_commit();

    for (int t = 0; t < NTILES; t++) {
        const int st = t & 1;
        if (t + 1 < NTILES) { copy_tile(st ^ 1, (t+1)*BK); cp_commit(); cp_wait<1>(); }
        else cp_wait<0>();
        __syncthreads();

        #pragma unroll
        for (int ks = 0; ks < BK/8; ks++) {
            uint32_t bfr[NT][2];
            #pragma unroll
            for (int nt = 0; nt < NT; nt++) {
                int nn = wnBase + nt*8 + lr;
                bfr[nt][0] = cvt_tf32(Ws[st][nn][ks*8 + lc]);
                bfr[nt][1] = cvt_tf32(Ws[st][nn][ks*8 + lc + 4]);
            }
            uint32_t afr[MT][4];
            #pragma unroll
            for (int mt = 0; mt < MT; mt++) {
                int rr = wmBase + mt*16 + lr;
                afr[mt][0] = cvt_tf32(As[st][rr][ks*8 + lc]);
                afr[mt][1] = cvt_tf32(As[st][rr + 8][ks*8 + lc]);
                afr[mt][2] = cvt_tf32(As[st][rr][ks*8 + lc + 4]);
                afr[mt][3] = cvt_tf32(As[st][rr + 8][ks*8 + lc + 4]);
            }
            #pragma unroll
            for (int mt = 0; mt < MT; mt++)
                #pragma unroll
                for (int nt = 0; nt < NT; nt++) {
                    asm volatile(
                        "mma.sync.aligned.m16n8k8.row.col.f32.tf32.tf32.f32 "
                        "{%0,%1,%2,%3}, {%4,%5,%6,%7}, {%8,%9}, {%0,%1,%2,%3};\n"
                        : "+f"(acc[mt][nt][0]), "+f"(acc[mt][nt][1]),
                          "+f"(acc[mt][nt][2]), "+f"(acc[mt][nt][3])
                        : "r"(afr[mt][0]), "r"(afr[mt][1]), "r"(afr[mt][2]), "r"(afr[mt][3]),
                          "r"(bfr[nt][0]), "r"(bfr[nt][1]));
                }
        }
        __syncthreads();
    }

    if (LNMODE == 0) {
        #pragma unroll
        for (int mt = 0; mt < MT; mt++) {
            #pragma unroll
            for (int nt = 0; nt < NT; nt++) {
                int row0 = rowBase + wmBase + mt*16 + lr;
                int col  = colBase + wnBase + nt*8 + 2*lc;
                float bx = 0.f, by = 0.f;
                if (bias) { bx = bias[col]; by = bias[col+1]; }
                float2 o0 = make_float2(acc[mt][nt][0] + bx, acc[mt][nt][1] + by);
                float2 o1 = make_float2(acc[mt][nt][2] + bx, acc[mt][nt][3] + by);
                if (relu) {
                    o0.x = fmaxf(o0.x, 0.f); o0.y = fmaxf(o0.y, 0.f);
                    o1.x = fmaxf(o1.x, 0.f); o1.y = fmaxf(o1.y, 0.f);
                }
                *reinterpret_cast<float2*>(C + (size_t)row0*Cout + col) = o0;
                *reinterpret_cast<float2*>(C + (size_t)(row0+8)*Cout + col) = o1;
            }
        }
    } else {
        float (*Cs)[BN + 4] = reinterpret_cast<float(*)[BN + 4]>(dsm);
        #pragma unroll
        for (int mt = 0; mt < MT; mt++) {
            #pragma unroll
            for (int nt = 0; nt < NT; nt++) {
                int r0 = wmBase + mt*16 + lr;
                int col = wnBase + nt*8 + 2*lc;
                float bx = bias[col], by = bias[col+1];
                *reinterpret_cast<float2*>(&Cs[r0][col]) =
                    make_float2(acc[mt][nt][0] + bx, acc[mt][nt][1] + by);
                *reinterpret_cast<float2*>(&Cs[r0 + 8][col]) =
                    make_float2(acc[mt][nt][2] + bx, acc[mt][nt][3] + by);
            }
        }
        __syncthreads();
        #pragma unroll
        for (int r = 0; r < BM/8; r++) {
            int row = wid * (BM/8) + r;
            float4 v = *reinterpret_cast<float4*>(&Cs[row][lane*4]);
            float s = v.x + v.y + v.z + v.w;
            float q = v.x*v.x + v.y*v.y + v.z*v.z + v.w*v.w;
            #pragma unroll
            for (int o = 16; o > 0; o >>= 1) {
                s += __shfl_xor_sync(0xffffffffu, s, o);
                q += __shfl_xor_sync(0xffffffffu, q, o);
            }
            float mu = s * (1.f/DIMF);
            float var = fmaxf(q * (1.f/DIMF) - mu*mu, 0.f);
            float rstd = rsqrtf(var + 1e-5f);
            int grow = rowBase + row;
            int rrow = gatherResid ? g_idxc[grow] : grow;
            float4 gv = *reinterpret_cast<const float4*>(lng + lane*4);
            float4 bv = *reinterpret_cast<const float4*>(lnb + lane*4);
            float4 rv = *reinterpret_cast<const float4*>(resid + (size_t)rrow*DIMF + lane*4);
            float4 o;
            o.x = (v.x - mu) * rstd * gv.x + bv.x + rv.x;
            o.y = (v.y - mu) * rstd * gv.y + bv.y + rv.y;
            o.z = (v.z - mu) * rstd * gv.z + bv.z + rv.z;
            o.w = (v.w - mu) * rstd * gv.w + bv.w + rv.w;
            *reinterpret_cast<float4*>(C + (size_t)grow*DIMF + lane*4) = o;
        }
    }
}

template<int BM, int BN, int WM, int WN>
__global__ __launch_bounds__(256, 3) void k_gemm(
    const float* __restrict__ A, const float* __restrict__ W,
    const float* __restrict__ bias, float* __restrict__ C,
    int Cin, int Cout, int relu)
{
    gemm_body<BM, BN, WM, WN, 0, 0>(A, W, bias, C, Cin, Cout, relu,
                                    nullptr, nullptr, nullptr, 0, nullptr);
}

template<int BM, int BN, int WM, int WN>
__global__ __launch_bounds__(256, 3) void k_gemm_ln(
    const float* __restrict__ A, const float* __restrict__ W,
    const float* __restrict__ bias, float* __restrict__ C, int Cin,
    const float* __restrict__ lng, const float* __restrict__ lnb,
    const float* __restrict__ resid, int gatherResid)
{
    gemm_body<BM, BN, WM, WN, 1, 0>(A, W, bias, C, Cin, DIMF, 0,
                                    lng, lnb, resid, gatherResid, nullptr);
}

// KV: z selects weight/output over all points
struct P2 { const float* W[2]; float* C[2]; };
__global__ __launch_bounds__(256, 3) void k_gemm_kv(const float* __restrict__ A, P2 p)
{
    gemm_body<64, 128, 32, 32, 0, 0>(A, p.W[blockIdx.z], nullptr, p.C[blockIdx.z],
                                     DIMF, DIMF, 0, nullptr, nullptr, nullptr, 0, nullptr);
}

// Q: gathered center rows only
__global__ __launch_bounds__(256, 3) void k_gemm_qg(
    const float* __restrict__ A, const float* __restrict__ W, float* __restrict__ C)
{
    gemm_body<64, 128, 32, 32, 0, 1>(A, W, nullptr, C, DIMF, DIMF, 0,
                                     nullptr, nullptr, nullptr, 0, g_idxc);
}

// smem byte counts (BK=16 pipeline, 2 stages)
#define GSM(BM_, BN_) (2 * ((BM_) + (BN_)) * 20 * 4)
#define LNSM(BM_, BN_) ((BM_) * ((BN_) + 4) * 4)
static const int SM_64  = GSM(64,128);    // 30720
static const int SM_LN  = GSM(32,128) > LNSM(32,128) ? GSM(32,128) : LNSM(32,128); // 25600

// ---------------- per-center attention (single gather pass, shuffle softmax) --
__global__ void k_attn() {
    __shared__ float q[DIMF];
    __shared__ float kS[KNB][DIMF + 4];
    __shared__ float vS[KNB][DIMF + 4];
    __shared__ int nbr_s[KNB];
    __shared__ int s_cnt;
    const int m = blockIdx.x, tid = threadIdx.x;
    if (tid < KNB) nbr_s[tid] = g_nbr[m*KNB + tid];
    if (tid == 0) s_cnt = g_cnt[m];
    q[tid] = g_Qc[(size_t)m*DIMF + tid] * 0.17677669529663687f;  // DH^-0.5
    __syncthreads();

    #pragma unroll
    for (int f = tid; f < KNB * (DIMF/4); f += 128) {
        int s = f >> 5, c4 = f & 31;
        size_t off = (size_t)nbr_s[s]*DIMF + c4*4;
        float4 kx = *reinterpret_cast<const float4*>(&g_Kp[off]);
        float4 vx = *reinterpret_cast<const float4*>(&g_Vp[off]);
        *reinterpret_cast<float4*>(&kS[s][c4*4]) = kx;
        *reinterpret_cast<float4*>(&vS[s][c4*4]) = vx;
    }
    __syncthreads();

    const int h = tid >> 5, lane = tid & 31;
    const int cnt = s_cnt;
    float logit = -1e9f;
    if (lane < cnt) {
        float a = 0.f;
        #pragma unroll
        for (int d = 0; d < DH; d++) a += q[h*DH + d] * kS[lane][h*DH + d];
        logit = a;
    }
    float mx = logit;
    #pragma unroll
    for (int o = 16; o > 0; o >>= 1) mx = fmaxf(mx, __shfl_xor_sync(0xffffffffu, mx, o));
    float e = (lane < cnt) ? expf(logit - mx) : 0.f;
    float sm = e;
    #pragma unroll
    for (int o = 16; o > 0; o >>= 1) sm += __shfl_xor_sync(0xffffffffu, sm, o);
    float w = e / sm;

    float acc = 0.f;
    #pragma unroll
    for (int kk = 0; kk < KNB; kk++)
        acc += __shfl_sync(0xffffffffu, w, kk) * vS[kk][h*DH + lane];
    g_ao[(size_t)m*DIMF + lane*NH + h] = acc;   // transpose(0,2,1) layout
}

// ---------------- final scatter: out = feats + c2[nearest] ----------------
__global__ void k_scatter(const float* __restrict__ feats, float* __restrict__ out) {
    int i = blockIdx.x * 256 + threadIdx.x;
    int n = i >> 5, c4 = i & 31;
    int ctr = (int)(g_nearKey[n] & 0xffffffffu);
    float4 f = *reinterpret_cast<const float4*>(feats + (size_t)n*DIMF + c4*4);
    float4 c = *reinterpret_cast<const float4*>(g_c2 + (size_t)ctr*DIMF + c4*4);
    f.x += c.x; f.y += c.y; f.z += c.z; f.w += c.w;
    *reinterpret_cast<float4*>(out + (size_t)n*DIMF + c4*4) = f;
}

// ---------------- launch (forked-stream graph) ----------------
extern "C" void kernel_launch(void* const* d_in, const int* in_sizes, int n_in,
                              void* d_out, int out_size) {
    const float* xyz   = (const float*)d_in[0];
    const float* feats = (const float*)d_in[1];
    const long long* idxc = (const long long*)d_in[2];
    const float* Wq = (const float*)d_in[3];
    const float* Wk = (const float*)d_in[4];
    const float* Wv = (const float*)d_in[5];
    const float* Wo = (const float*)d_in[6];
    const float* bo = (const float*)d_in[7];
    const float* g1 = (const float*)d_in[8];
    const float* be1 = (const float*)d_in[9];
    const float* g2 = (const float*)d_in[10];
    const float* be2 = (const float*)d_in[11];
    const float* W1 = (const float*)d_in[12];
    const float* b1f = (const float*)d_in[13];
    const float* W2 = (const float*)d_in[14];
    const float* b2f = (const float*)d_in[15];
    float* out = (float*)d_out;

    float *qc, *kp, *vp, *ao, *c1, *hid, *c2;
    cudaGetSymbolAddress((void**)&qc,  g_Qc);
    cudaGetSymbolAddress((void**)&kp,  g_Kp);
    cudaGetSymbolAddress((void**)&vp,  g_Vp);
    cudaGetSymbolAddress((void**)&ao,  g_ao);
    cudaGetSymbolAddress((void**)&c1,  g_c1);
    cudaGetSymbolAddress((void**)&hid, g_hid);
    cudaGetSymbolAddress((void**)&c2,  g_c2);

    static cudaStream_t s1 = nullptr, s2 = nullptr;
    static cudaEvent_t eFork = nullptr, eTopk = nullptr, eNear = nullptr;
    if (!s1) {
        cudaStreamCreateWithFlags(&s1, cudaStreamNonBlocking);
        cudaStreamCreateWithFlags(&s2, cudaStreamNonBlocking);
        cudaEventCreateWithFlags(&eFork, cudaEventDisableTiming);
        cudaEventCreateWithFlags(&eTopk, cudaEventDisableTiming);
        cudaEventCreateWithFlags(&eNear, cudaEventDisableTiming);
    }
    cudaStream_t s0 = 0;

    k_init<<<NPTS/256, 256, 0, s0>>>(xyz, idxc);
    cudaEventRecord(eFork, s0);

    cudaStreamWaitEvent(s1, eFork, 0);
    cudaStreamWaitEvent(s2, eFork, 0);
    k_topk<<<MC/CPB, 256, 0, s1>>>();
    cudaEventRecord(eTopk, s1);
    k_nearest<<<dim3(NPTS/1024, MC/CCH), 256, 0, s2>>>();
    cudaEventRecord(eNear, s2);

    // Q over gathered centers (64 blocks), then K,V over all points (512 blocks)
    k_gemm_qg<<<dim3(MC/64, 1), 256, SM_64, s0>>>(feats, Wq, qc);
    P2 p;
    p.W[0] = Wk; p.W[1] = Wv;
    p.C[0] = kp; p.C[1] = vp;
    k_gemm_kv<<<dim3(NPTS/64, 1, 2), 256, SM_64, s0>>>(feats, p);

    cudaStreamWaitEvent(s0, eTopk, 0);
    k_attn<<<MC, 128, 0, s0>>>();

    // Wo GEMM + LN1 + residual(feats gathered by idxc) -> c1   (128 blocks)
    k_gemm_ln<32,128,16,32><<<dim3(MC/32, 1), 256, SM_LN, s0>>>(
        ao, Wo, bo, c1, DIMF, g1, be1, feats, 1);
    // FFN up (relu)   (256 blocks)
    k_gemm<64,128,32,32><<<dim3(MC/64, HID/128), 256, SM_64, s0>>>(
        c1, W1, b1f, hid, DIMF, HID, 1);
    // FFN down + LN2 + residual(c1) -> c2   (128 blocks)
    k_gemm_ln<32,128,16,32><<<dim3(MC/32, 1), 256, SM_LN, s0>>>(
        hid, W2, b2f, c2, HID, g2, be2, c1, 0);

    cudaStreamWaitEvent(s0, eNear, 0);
    k_scatter<<<NPTS*(DIMF/4)/256, 256, 0, s0>>>(feats, out);
}